// round 10
// baseline (speedup 1.0000x reference)
#include <cuda_runtime.h>

// Direction table: E = 2,000,000 edges; float4 for 16B-aligned gathers.
// 2.1M * 16B = 33.6 MB static __device__ array; fully L2-resident (126 MB L2).
#define MAX_E   2100000
#define TILE    512          // pairs per staged tile (256 threads * 2 pairs)
#define NBLOCKS 1184         // 148 SMs * 8

static __device__ float4 g_dir[MAX_E];
static __device__ int    g_idx_is64;

// ---------------------------------------------------------------------------
// Helpers
// ---------------------------------------------------------------------------
__device__ __forceinline__ unsigned long long evict_last_policy()
{
    unsigned long long pol;
    asm volatile("createpolicy.fractional.L2::evict_last.b64 %0, 1.0;" : "=l"(pol));
    return pol;
}

__device__ __forceinline__ float4 ldg_table(const float4* p, unsigned long long pol)
{
    float4 v;
    asm volatile("ld.global.nc.L2::cache_hint.v4.f32 {%0,%1,%2,%3}, [%4], %5;"
                 : "=f"(v.x), "=f"(v.y), "=f"(v.z), "=f"(v.w)
                 : "l"(p), "l"(pol));
    return v;
}

__device__ __forceinline__ void stcs_f2(float2* p, float2 v)
{
    asm volatile("st.global.cs.v2.f32 [%0], {%1,%2};"
                 :: "l"(p), "f"(v.x), "f"(v.y) : "memory");
}

__device__ __forceinline__ unsigned sm_addr(const void* p)
{
    return (unsigned)__cvta_generic_to_shared(p);
}

__device__ __forceinline__ void mbar_init(unsigned mb, unsigned cnt)
{
    asm volatile("mbarrier.init.shared.b64 [%0], %1;" :: "r"(mb), "r"(cnt) : "memory");
}

__device__ __forceinline__ void mbar_expect_tx(unsigned mb, unsigned tx)
{
    asm volatile("mbarrier.arrive.expect_tx.shared.b64 _, [%0], %1;"
                 :: "r"(mb), "r"(tx) : "memory");
}

__device__ __forceinline__ void bulk_g2s(unsigned dst, const void* src,
                                         unsigned bytes, unsigned mb)
{
    asm volatile("cp.async.bulk.shared::cta.global.mbarrier::complete_tx::bytes "
                 "[%0], [%1], %2, [%3];"
                 :: "r"(dst), "l"(src), "r"(bytes), "r"(mb) : "memory");
}

__device__ __forceinline__ void mbar_wait(unsigned mb, unsigned parity)
{
    unsigned done;
    asm volatile("{\n\t.reg .pred p;\n\t"
                 "mbarrier.try_wait.parity.acquire.cta.shared::cta.b64 p, [%1], %2;\n\t"
                 "selp.b32 %0, 1, 0, p;\n\t}"
                 : "=r"(done) : "r"(mb), "r"(parity) : "memory");
    if (!done) {
        asm volatile("{\n\t.reg .pred P1;\n\t"
                     "WL%=:\n\t"
                     "mbarrier.try_wait.parity.acquire.cta.shared::cta.b64 P1, [%0], %1, 0x989680;\n\t"
                     "@P1 bra.uni WD%=;\n\t"
                     "bra.uni WL%=;\n\t"
                     "WD%=:\n\t}"
                     :: "r"(mb), "r"(parity) : "memory");
    }
}

// ---------------------------------------------------------------------------
// Pass 1: dir[i] = vec[i] / max(dist[i], 1e-5).
// Block 0 / warp 0 additionally detects int64-vs-int32 indices:
// int64 little-endian with values < 2M -> odd 32-bit words are all zero.
// ---------------------------------------------------------------------------
__global__ void dir_kernel(const float* __restrict__ dist,
                           const float* __restrict__ vec,
                           const unsigned int* __restrict__ idx_words,
                           int n_pairs,
                           int E)
{
    if (blockIdx.x == 0 && threadIdx.x < 32) {
        int n = n_pairs < 256 ? n_pairs : 256;
        int lane = threadIdx.x;
        int zeros = 0;
        for (int j = lane; j < n; j += 32)
            zeros += (idx_words[2 * j + 1] == 0u) ? 1 : 0;
        #pragma unroll
        for (int off = 16; off > 0; off >>= 1)
            zeros += __shfl_down_sync(0xFFFFFFFFu, zeros, off);
        if (lane == 0)
            g_idx_is64 = (zeros >= (n * 3) / 4) ? 1 : 0;
    }

    int i = blockIdx.x * blockDim.x + threadIdx.x;
    if (i >= E) return;
    float inv = 1.0f / fmaxf(dist[i], 1e-5f);
    float x = vec[3 * i + 0] * inv;
    float y = vec[3 * i + 1] * inv;
    float z = vec[3 * i + 2] * inv;
    g_dir[i] = make_float4(x, y, z, 0.0f);
}

// ---------------------------------------------------------------------------
// Pass 2: double-buffered cp.async.bulk staging of index tiles into SMEM
// (keeps the index streams off the L1tex wavefront port), evict-last table
// gathers, streamed vector output stores. 512 pairs/tile, 2 pairs/thread.
// ---------------------------------------------------------------------------
__global__ void __launch_bounds__(256) angle_kernel(
        const char* __restrict__ src_v,
        const char* __restrict__ dst_v,
        float* __restrict__ out,
        int A)
{
    // [stage][src(0)/dst(1)] each sub-buffer sized for int64 worst case.
    __shared__ __align__(128) char sbuf[2][2][TILE * 8];
    __shared__ __align__(8)   unsigned long long mbar[2];

    const int tid  = threadIdx.x;
    const int is64 = g_idx_is64;
    const unsigned tb = TILE * (is64 ? 8u : 4u);   // bytes per index tile
    const int ntiles = A / TILE;

    const unsigned mb_base = sm_addr(&mbar[0]);
    const unsigned sb_base = sm_addr(&sbuf[0][0][0]);
    const unsigned STAGE_BYTES = 2u * TILE * 8u;   // 8192

    if (tid == 0) {
        mbar_init(mb_base,      1);
        mbar_init(mb_base + 8u, 1);
    }
    __syncthreads();

    unsigned long long pol = evict_last_policy();

    int ph0 = 0, ph1 = 0;
    int t = blockIdx.x;

    // Prologue: issue tile t into stage 0.
    if (t < ntiles && tid == 0) {
        mbar_expect_tx(mb_base, 2u * tb);
        bulk_g2s(sb_base,             src_v + (size_t)t * tb, tb, mb_base);
        bulk_g2s(sb_base + TILE * 8u, dst_v + (size_t)t * tb, tb, mb_base);
    }

    int k = 0;
    for (; t < ntiles; t += gridDim.x, ++k) {
        const int s = k & 1;

        // Prefetch next tile into the other stage (free since prev iter's
        // trailing __syncthreads guarantees it was fully consumed).
        int tn = t + gridDim.x;
        if (tn < ntiles && tid == 0) {
            const int s2 = s ^ 1;
            unsigned mbs2 = mb_base + (unsigned)s2 * 8u;
            unsigned sb2  = sb_base + (unsigned)s2 * STAGE_BYTES;
            mbar_expect_tx(mbs2, 2u * tb);
            bulk_g2s(sb2,             src_v + (size_t)tn * tb, tb, mbs2);
            bulk_g2s(sb2 + TILE * 8u, dst_v + (size_t)tn * tb, tb, mbs2);
        }

        // Wait for current stage.
        unsigned mbs = mb_base + (unsigned)s * 8u;
        int ph = s ? ph1 : ph0;
        mbar_wait(mbs, ph & 1);
        if (s) ph1++; else ph0++;

        // Process 2 pairs per thread from SMEM indices.
        const char* stage_p = &sbuf[0][0][0] + (size_t)s * STAGE_BYTES;
        int li = tid * 2;
        int s0, s1, d0, d1;
        if (is64) {
            const long long* sp = (const long long*)stage_p;
            const long long* dp = (const long long*)(stage_p + TILE * 8);
            s0 = (int)sp[li]; s1 = (int)sp[li + 1];
            d0 = (int)dp[li]; d1 = (int)dp[li + 1];
        } else {
            const int* sp = (const int*)stage_p;
            const int* dp = (const int*)(stage_p + TILE * 8);
            s0 = sp[li]; s1 = sp[li + 1];
            d0 = dp[li]; d1 = dp[li + 1];
        }

        float4 a0 = ldg_table(&g_dir[s0], pol);
        float4 b0 = ldg_table(&g_dir[d0], pol);
        float4 a1 = ldg_table(&g_dir[s1], pol);
        float4 b1 = ldg_table(&g_dir[d1], pol);

        float c0 = a0.x * b0.x + a0.y * b0.y + a0.z * b0.z;
        float c1 = a1.x * b1.x + a1.y * b1.y + a1.z * b1.z;
        float2 r = make_float2(acosf(0.95f * c0), acosf(0.95f * c1));
        stcs_f2((float2*)(out + (size_t)t * TILE + li), r);

        __syncthreads();  // all threads done reading stage s before refill
    }

    // Tail pairs (A % TILE), scalar on block 0.
    if (blockIdx.x == 0) {
        for (int i = ntiles * TILE + tid; i < A; i += blockDim.x) {
            int si, di;
            if (is64) {
                si = (int)((const long long*)src_v)[i];
                di = (int)((const long long*)dst_v)[i];
            } else {
                si = ((const int*)src_v)[i];
                di = ((const int*)dst_v)[i];
            }
            float4 a = ldg_table(&g_dir[si], pol);
            float4 b = ldg_table(&g_dir[di], pol);
            float c = a.x * b.x + a.y * b.y + a.z * b.z;
            out[i] = acosf(0.95f * c);
        }
    }
}

// ---------------------------------------------------------------------------
// Launch
// inputs (metadata order): distances [E] f32, vec [E,3] f32,
//                          angle_src [A] i64/i32, angle_dst [A] i64/i32
// output: angles [A] f32
// ---------------------------------------------------------------------------
extern "C" void kernel_launch(void* const* d_in, const int* in_sizes, int n_in,
                              void* d_out, int out_size)
{
    const float* dist = (const float*)d_in[0];
    const float* vec  = (const float*)d_in[1];
    const char*  src  = (const char*)d_in[2];
    const char*  dst  = (const char*)d_in[3];
    float*       out  = (float*)d_out;

    int E = in_sizes[0];
    int A = in_sizes[2];
    if (E > MAX_E) E = MAX_E;

    const int T = 256;
    dir_kernel<<<(E + T - 1) / T, T>>>(dist, vec, (const unsigned int*)src, A, E);

    angle_kernel<<<NBLOCKS, T>>>(src, dst, out, A);
}

// round 12
// speedup vs baseline: 1.0376x; 1.0376x over previous
#include <cuda_runtime.h>

// Direction table: E = 2,000,000 edges; float4 for 16B-aligned gathers.
// 2.1M * 16B = 33.6 MB static __device__ array; fully L2-resident (126 MB L2).
#define MAX_E 2100000

static __device__ float4 g_dir[MAX_E];
static __device__ int    g_idx_is64;

// ---------------------------------------------------------------------------
// Cache-policy load/store helpers
// ---------------------------------------------------------------------------
__device__ __forceinline__ unsigned long long evict_last_policy()
{
    unsigned long long pol;
    asm volatile("createpolicy.fractional.L2::evict_last.b64 %0, 1.0;" : "=l"(pol));
    return pol;
}

__device__ __forceinline__ float4 ldg_table(const float4* p, unsigned long long pol)
{
    float4 v;
    asm volatile("ld.global.nc.L2::cache_hint.v4.f32 {%0,%1,%2,%3}, [%4], %5;"
                 : "=f"(v.x), "=f"(v.y), "=f"(v.z), "=f"(v.w)
                 : "l"(p), "l"(pol));
    return v;
}

__device__ __forceinline__ void stg_table(float4* p, float4 v, unsigned long long pol)
{
    asm volatile("st.global.L2::cache_hint.v4.f32 [%0], {%1,%2,%3,%4}, %5;"
                 :: "l"(p), "f"(v.x), "f"(v.y), "f"(v.z), "f"(v.w), "l"(pol)
                 : "memory");
}

__device__ __forceinline__ longlong2 ldcs_ll2(const longlong2* p)
{
    longlong2 v;
    asm volatile("ld.global.cs.v2.s64 {%0,%1}, [%2];"
                 : "=l"(v.x), "=l"(v.y) : "l"(p));
    return v;
}

__device__ __forceinline__ int4 ldcs_i4(const int4* p)
{
    int4 v;
    asm volatile("ld.global.cs.v4.s32 {%0,%1,%2,%3}, [%4];"
                 : "=r"(v.x), "=r"(v.y), "=r"(v.z), "=r"(v.w) : "l"(p));
    return v;
}

__device__ __forceinline__ void stcs_f4(float4* p, float4 v)
{
    asm volatile("st.global.cs.v4.f32 [%0], {%1,%2,%3,%4};"
                 :: "l"(p), "f"(v.x), "f"(v.y), "f"(v.z), "f"(v.w) : "memory");
}

// ---------------------------------------------------------------------------
// Pass 1: dir[i] = vec[i] / max(dist[i], 1e-5), 4 edges per thread with
// fully vectorized float4 loads (1x dist, 3x vec) and evict-last table
// stores (primes L2 residency priority for the gather phase).
// Block 0 / warp 0 additionally detects int64-vs-int32 indices:
// int64 little-endian with values < 2M -> odd 32-bit words are all zero.
// ---------------------------------------------------------------------------
__global__ void dir_kernel(const float* __restrict__ dist,
                           const float* __restrict__ vec,
                           const unsigned int* __restrict__ idx_words,
                           int n_pairs,
                           int E)
{
    if (blockIdx.x == 0 && threadIdx.x < 32) {
        int n = n_pairs < 256 ? n_pairs : 256;
        int lane = threadIdx.x;
        int zeros = 0;
        for (int j = lane; j < n; j += 32)
            zeros += (idx_words[2 * j + 1] == 0u) ? 1 : 0;
        #pragma unroll
        for (int off = 16; off > 0; off >>= 1)
            zeros += __shfl_down_sync(0xFFFFFFFFu, zeros, off);
        if (lane == 0)
            g_idx_is64 = (zeros >= (n * 3) / 4) ? 1 : 0;
    }

    unsigned long long pol = evict_last_policy();
    int t  = blockIdx.x * blockDim.x + threadIdx.x;
    int i0 = t * 4;
    if (i0 >= E) return;

    if (i0 + 3 < E) {
        float4 d4 = *(const float4*)(dist + i0);
        float4 v0 = *(const float4*)(vec + 3 * i0);      // e0.xyz, e1.x
        float4 v1 = *(const float4*)(vec + 3 * i0 + 4);  // e1.yz, e2.xy
        float4 v2 = *(const float4*)(vec + 3 * i0 + 8);  // e2.z, e3.xyz

        float r0 = 1.0f / fmaxf(d4.x, 1e-5f);
        float r1 = 1.0f / fmaxf(d4.y, 1e-5f);
        float r2 = 1.0f / fmaxf(d4.z, 1e-5f);
        float r3 = 1.0f / fmaxf(d4.w, 1e-5f);

        stg_table(&g_dir[i0 + 0], make_float4(v0.x * r0, v0.y * r0, v0.z * r0, 0.0f), pol);
        stg_table(&g_dir[i0 + 1], make_float4(v0.w * r1, v1.x * r1, v1.y * r1, 0.0f), pol);
        stg_table(&g_dir[i0 + 2], make_float4(v1.z * r2, v1.w * r2, v2.x * r2, 0.0f), pol);
        stg_table(&g_dir[i0 + 3], make_float4(v2.y * r3, v2.z * r3, v2.w * r3, 0.0f), pol);
    } else {
        for (int i = i0; i < E; ++i) {
            float inv = 1.0f / fmaxf(dist[i], 1e-5f);
            stg_table(&g_dir[i],
                      make_float4(vec[3 * i] * inv, vec[3 * i + 1] * inv,
                                  vec[3 * i + 2] * inv, 0.0f), pol);
        }
    }
}

// ---------------------------------------------------------------------------
// Pass 2: 4 angle pairs per thread, gathers in two batches of 4 to keep the
// live register set <= 32 regs (launch_bounds(256,8) -> high occupancy).
// Streamed index loads (evict-first), evict-last table gathers, streamed
// vector output stores.
// ---------------------------------------------------------------------------
__global__ void __launch_bounds__(256, 8) angle_kernel(
        const void* __restrict__ src_v,
        const void* __restrict__ dst_v,
        float* __restrict__ out,
        int A)
{
    int t  = blockIdx.x * blockDim.x + threadIdx.x;
    int i0 = t * 4;
    if (i0 >= A) return;

    unsigned long long pol = evict_last_policy();
    const int is64 = g_idx_is64;

    if (i0 + 3 < A) {
        int s[4], d[4];
        if (is64) {
            const long long* sp = (const long long*)src_v + i0;
            const long long* dp = (const long long*)dst_v + i0;
            longlong2 sa = ldcs_ll2((const longlong2*)sp);
            longlong2 sb = ldcs_ll2((const longlong2*)(sp + 2));
            longlong2 da = ldcs_ll2((const longlong2*)dp);
            longlong2 db = ldcs_ll2((const longlong2*)(dp + 2));
            s[0] = (int)sa.x; s[1] = (int)sa.y; s[2] = (int)sb.x; s[3] = (int)sb.y;
            d[0] = (int)da.x; d[1] = (int)da.y; d[2] = (int)db.x; d[3] = (int)db.y;
        } else {
            int4 sa = ldcs_i4((const int4*)((const int*)src_v + i0));
            int4 da = ldcs_i4((const int4*)((const int*)dst_v + i0));
            s[0] = sa.x; s[1] = sa.y; s[2] = sa.z; s[3] = sa.w;
            d[0] = da.x; d[1] = da.y; d[2] = da.z; d[3] = da.w;
        }

        // Batch 1: 4 gathers in flight, consume, release registers.
        float4 a0 = ldg_table(&g_dir[s[0]], pol);
        float4 b0 = ldg_table(&g_dir[d[0]], pol);
        float4 a1 = ldg_table(&g_dir[s[1]], pol);
        float4 b1 = ldg_table(&g_dir[d[1]], pol);
        float c0 = a0.x * b0.x + a0.y * b0.y + a0.z * b0.z;
        float c1 = a1.x * b1.x + a1.y * b1.y + a1.z * b1.z;
        float r0 = acosf(0.95f * c0);
        float r1 = acosf(0.95f * c1);

        // Batch 2.
        float4 a2 = ldg_table(&g_dir[s[2]], pol);
        float4 b2 = ldg_table(&g_dir[d[2]], pol);
        float4 a3 = ldg_table(&g_dir[s[3]], pol);
        float4 b3 = ldg_table(&g_dir[d[3]], pol);
        float c2 = a2.x * b2.x + a2.y * b2.y + a2.z * b2.z;
        float c3 = a3.x * b3.x + a3.y * b3.y + a3.z * b3.z;

        float4 r = make_float4(r0, r1, acosf(0.95f * c2), acosf(0.95f * c3));
        stcs_f4((float4*)(out + i0), r);
    } else {
        for (int i = i0; i < A; ++i) {
            int si, di;
            if (is64) {
                si = (int)((const long long*)src_v)[i];
                di = (int)((const long long*)dst_v)[i];
            } else {
                si = ((const int*)src_v)[i];
                di = ((const int*)dst_v)[i];
            }
            float4 a = ldg_table(&g_dir[si], pol);
            float4 b = ldg_table(&g_dir[di], pol);
            float c = a.x * b.x + a.y * b.y + a.z * b.z;
            out[i] = acosf(0.95f * c);
        }
    }
}

// ---------------------------------------------------------------------------
// Launch
// inputs (metadata order): distances [E] f32, vec [E,3] f32,
//                          angle_src [A] i64/i32, angle_dst [A] i64/i32
// output: angles [A] f32
// ---------------------------------------------------------------------------
extern "C" void kernel_launch(void* const* d_in, const int* in_sizes, int n_in,
                              void* d_out, int out_size)
{
    const float* dist = (const float*)d_in[0];
    const float* vec  = (const float*)d_in[1];
    const void*  src  = d_in[2];
    const void*  dst  = d_in[3];
    float*       out  = (float*)d_out;

    int E = in_sizes[0];
    int A = in_sizes[2];
    if (E > MAX_E) E = MAX_E;

    const int T = 256;
    int dir_threads = (E + 3) / 4;
    dir_kernel<<<(dir_threads + T - 1) / T, T>>>(dist, vec, (const unsigned int*)src, A, E);

    int threads_needed = (A + 3) / 4;
    angle_kernel<<<(threads_needed + T - 1) / T, T>>>(src, dst, out, A);
}

// round 13
// speedup vs baseline: 1.0779x; 1.0389x over previous
#include <cuda_runtime.h>

// Direction table: E = 2,000,000 edges; float4 for 16B-aligned gathers.
// 2.1M * 16B = 33.6 MB static __device__ array; fully L2-resident (126 MB L2).
#define MAX_E 2100000

static __device__ float4 g_dir[MAX_E];
static __device__ int    g_idx_is64;

// ---------------------------------------------------------------------------
// Cache-policy load/store helpers
// ---------------------------------------------------------------------------
__device__ __forceinline__ unsigned long long evict_last_policy()
{
    unsigned long long pol;
    asm volatile("createpolicy.fractional.L2::evict_last.b64 %0, 1.0;" : "=l"(pol));
    return pol;
}

__device__ __forceinline__ float4 ldg_table(const float4* p, unsigned long long pol)
{
    float4 v;
    asm volatile("ld.global.nc.L2::cache_hint.v4.f32 {%0,%1,%2,%3}, [%4], %5;"
                 : "=f"(v.x), "=f"(v.y), "=f"(v.z), "=f"(v.w)
                 : "l"(p), "l"(pol));
    return v;
}

__device__ __forceinline__ longlong2 ldcs_ll2(const longlong2* p)
{
    longlong2 v;
    asm volatile("ld.global.cs.v2.s64 {%0,%1}, [%2];"
                 : "=l"(v.x), "=l"(v.y) : "l"(p));
    return v;
}

__device__ __forceinline__ int4 ldcs_i4(const int4* p)
{
    int4 v;
    asm volatile("ld.global.cs.v4.s32 {%0,%1,%2,%3}, [%4];"
                 : "=r"(v.x), "=r"(v.y), "=r"(v.z), "=r"(v.w) : "l"(p));
    return v;
}

__device__ __forceinline__ void stcs_f4(float4* p, float4 v)
{
    asm volatile("st.global.cs.v4.f32 [%0], {%1,%2,%3,%4};"
                 :: "l"(p), "f"(v.x), "f"(v.y), "f"(v.z), "f"(v.w) : "memory");
}

__device__ __forceinline__ void pdl_launch_dependents()
{
    asm volatile("griddepcontrol.launch_dependents;");
}

__device__ __forceinline__ void pdl_wait()
{
    asm volatile("griddepcontrol.wait;");
}

// ---------------------------------------------------------------------------
// Pass 1: dir[i] = vec[i] / max(dist[i], 1e-5)  (scalar loads: consecutive
// threads read consecutive floats -> fully coalesced; R12's 4-edge float4
// version had 48B lane stride and regressed).
// Block 0 / warp 0 detects int64-vs-int32 indices first; all blocks then
// trigger PDL so the angle kernel can start its index prologue while this
// kernel finishes normalizing.
// ---------------------------------------------------------------------------
__global__ void dir_kernel(const float* __restrict__ dist,
                           const float* __restrict__ vec,
                           const unsigned int* __restrict__ idx_words,
                           int n_pairs,
                           int E)
{
    if (blockIdx.x == 0 && threadIdx.x < 32) {
        int n = n_pairs < 256 ? n_pairs : 256;
        int lane = threadIdx.x;
        int zeros = 0;
        for (int j = lane; j < n; j += 32)
            zeros += (idx_words[2 * j + 1] == 0u) ? 1 : 0;
        #pragma unroll
        for (int off = 16; off > 0; off >>= 1)
            zeros += __shfl_down_sync(0xFFFFFFFFu, zeros, off);
        if (lane == 0) {
            g_idx_is64 = (zeros >= (n * 3) / 4) ? 1 : 0;
            __threadfence();
        }
    }
    // Ensure block 0's flag write precedes this block's trigger contribution.
    __syncthreads();
    pdl_launch_dependents();

    int i = blockIdx.x * blockDim.x + threadIdx.x;
    if (i >= E) return;
    float inv = 1.0f / fmaxf(dist[i], 1e-5f);
    float x = vec[3 * i + 0] * inv;
    float y = vec[3 * i + 1] * inv;
    float z = vec[3 * i + 2] * inv;
    g_dir[i] = make_float4(x, y, z, 0.0f);
}

// ---------------------------------------------------------------------------
// Pass 2: 4 angle pairs per thread, gathers in two batches of 4 to keep the
// live register set <= 32 regs (launch_bounds(256,8) -> high occupancy).
// Launched with programmatic stream serialization: index loads run
// concurrently with dir_kernel's tail; griddepcontrol.wait gates the table
// gathers on dir_kernel completion.
// ---------------------------------------------------------------------------
__global__ void __launch_bounds__(256, 8) angle_kernel(
        const void* __restrict__ src_v,
        const void* __restrict__ dst_v,
        float* __restrict__ out,
        int A)
{
    int t  = blockIdx.x * blockDim.x + threadIdx.x;
    int i0 = t * 4;
    if (i0 >= A) { pdl_wait(); return; }

    unsigned long long pol = evict_last_policy();
    const int is64 = g_idx_is64;   // written before dir_kernel's PDL trigger

    if (i0 + 3 < A) {
        int s[4], d[4];
        if (is64) {
            const long long* sp = (const long long*)src_v + i0;
            const long long* dp = (const long long*)dst_v + i0;
            longlong2 sa = ldcs_ll2((const longlong2*)sp);
            longlong2 sb = ldcs_ll2((const longlong2*)(sp + 2));
            longlong2 da = ldcs_ll2((const longlong2*)dp);
            longlong2 db = ldcs_ll2((const longlong2*)(dp + 2));
            s[0] = (int)sa.x; s[1] = (int)sa.y; s[2] = (int)sb.x; s[3] = (int)sb.y;
            d[0] = (int)da.x; d[1] = (int)da.y; d[2] = (int)db.x; d[3] = (int)db.y;
        } else {
            int4 sa = ldcs_i4((const int4*)((const int*)src_v + i0));
            int4 da = ldcs_i4((const int4*)((const int*)dst_v + i0));
            s[0] = sa.x; s[1] = sa.y; s[2] = sa.z; s[3] = sa.w;
            d[0] = da.x; d[1] = da.y; d[2] = da.z; d[3] = da.w;
        }

        // Gate the table gathers on dir_kernel completion.
        pdl_wait();

        // Batch 1: 4 gathers in flight, consume, release registers.
        float4 a0 = ldg_table(&g_dir[s[0]], pol);
        float4 b0 = ldg_table(&g_dir[d[0]], pol);
        float4 a1 = ldg_table(&g_dir[s[1]], pol);
        float4 b1 = ldg_table(&g_dir[d[1]], pol);
        float c0 = a0.x * b0.x + a0.y * b0.y + a0.z * b0.z;
        float c1 = a1.x * b1.x + a1.y * b1.y + a1.z * b1.z;
        float r0 = acosf(0.95f * c0);
        float r1 = acosf(0.95f * c1);

        // Batch 2.
        float4 a2 = ldg_table(&g_dir[s[2]], pol);
        float4 b2 = ldg_table(&g_dir[d[2]], pol);
        float4 a3 = ldg_table(&g_dir[s[3]], pol);
        float4 b3 = ldg_table(&g_dir[d[3]], pol);
        float c2 = a2.x * b2.x + a2.y * b2.y + a2.z * b2.z;
        float c3 = a3.x * b3.x + a3.y * b3.y + a3.z * b3.z;

        float4 r = make_float4(r0, r1, acosf(0.95f * c2), acosf(0.95f * c3));
        stcs_f4((float4*)(out + i0), r);
    } else {
        pdl_wait();
        for (int i = i0; i < A; ++i) {
            int si, di;
            if (is64) {
                si = (int)((const long long*)src_v)[i];
                di = (int)((const long long*)dst_v)[i];
            } else {
                si = ((const int*)src_v)[i];
                di = ((const int*)dst_v)[i];
            }
            float4 a = ldg_table(&g_dir[si], pol);
            float4 b = ldg_table(&g_dir[di], pol);
            float c = a.x * b.x + a.y * b.y + a.z * b.z;
            out[i] = acosf(0.95f * c);
        }
    }
}

// ---------------------------------------------------------------------------
// Launch
// inputs (metadata order): distances [E] f32, vec [E,3] f32,
//                          angle_src [A] i64/i32, angle_dst [A] i64/i32
// output: angles [A] f32
// ---------------------------------------------------------------------------
extern "C" void kernel_launch(void* const* d_in, const int* in_sizes, int n_in,
                              void* d_out, int out_size)
{
    const float* dist = (const float*)d_in[0];
    const float* vec  = (const float*)d_in[1];
    const void*  src  = d_in[2];
    const void*  dst  = d_in[3];
    float*       out  = (float*)d_out;

    int E = in_sizes[0];
    int A = in_sizes[2];
    if (E > MAX_E) E = MAX_E;

    const int T = 256;
    dir_kernel<<<(E + T - 1) / T, T>>>(dist, vec, (const unsigned int*)src, A, E);

    // Angle kernel with programmatic dependent launch: overlaps its index
    // prologue with dir_kernel's tail.
    int threads_needed = (A + 3) / 4;
    int blocks = (threads_needed + T - 1) / T;

    cudaLaunchConfig_t cfg = {};
    cfg.gridDim  = dim3((unsigned)blocks, 1, 1);
    cfg.blockDim = dim3((unsigned)T, 1, 1);
    cfg.dynamicSmemBytes = 0;
    cfg.stream = 0;

    cudaLaunchAttribute attrs[1];
    attrs[0].id = cudaLaunchAttributeProgrammaticStreamSerialization;
    attrs[0].val.programmaticStreamSerializationAllowed = 1;
    cfg.attrs = attrs;
    cfg.numAttrs = 1;

    cudaLaunchKernelEx(&cfg, angle_kernel, (const void*)src, (const void*)dst, out, A);
}